// round 15
// baseline (speedup 1.0000x reference)
#include <cuda_runtime.h>
#include <cuda_fp16.h>
#include <cstdint>

#define NN 128

// ---- packed global operands (fp16 planes, packed 2/word) -------------------
__device__ uint32_t g_xA[1024u * 8192u];      // x A-fmt [tile(b,t)]: hi r*64+kp (4096), lo +4096
__device__ uint32_t g_xB[1024u * 4096u];      // x B64 1-plane [tile(b,t)]: n*32+kpf
__device__ uint32_t g_SB[2048u * 8192u];      // S B-fmt 1-plane [tile(b,t,e)]: half0 | half1
__device__ uint32_t g_tapA[2][2048u * 4096u]; // taps 1,2 A-fmt 1-plane [tile(b,t,e)]
__device__ uint32_t g_tapB[3][2048u * 4096u]; // taps 1,2,3 B64 1-plane [tile(b,t,e)]
__device__ uint32_t g_HA[8u * 4096u];         // H chunks [e*4+k]: hi o*32+kpf (2048), lo +2048

// ---------------------------------------------------------------------------
__device__ __forceinline__ uint32_t pack_h2(float a, float b) {
    uint32_t ua = (uint32_t)__half_as_ushort(__float2half_rn(a));
    uint32_t ub = (uint32_t)__half_as_ushort(__float2half_rn(b));
    return (ub << 16) | ua;
}
__device__ __forceinline__ uint32_t pack_l2(float a, float b) {
    __half ha = __float2half_rn(a), hb = __float2half_rn(b);
    float ra = a - __half2float(ha), rb = b - __half2float(hb);
    uint32_t ua = (uint32_t)__half_as_ushort(__float2half_rn(ra));
    uint32_t ub = (uint32_t)__half_as_ushort(__float2half_rn(rb));
    return (ub << 16) | ua;
}
__device__ __forceinline__ uint32_t smem_u32(const void* p) {
    uint32_t a;
    asm("{ .reg .u64 t; cvta.to.shared.u64 t, %1; cvt.u32.u64 %0, t; }" : "=r"(a) : "l"(p));
    return a;
}
__device__ __forceinline__ void ldsm4(uint32_t a, uint32_t& r0, uint32_t& r1,
                                      uint32_t& r2, uint32_t& r3) {
    asm volatile("ldmatrix.sync.aligned.m8n8.x4.shared.b16 {%0,%1,%2,%3}, [%4];"
                 : "=r"(r0), "=r"(r1), "=r"(r2), "=r"(r3) : "r"(a));
}

#define MMA_F16(c, a0, a1, a2, a3, b0, b1)                                    \
    asm volatile(                                                             \
        "mma.sync.aligned.m16n8k16.row.col.f32.f16.f16.f32 "                  \
        "{%0,%1,%2,%3}, {%4,%5,%6,%7}, {%8,%9}, {%0,%1,%2,%3};"               \
        : "+f"((c)[0]), "+f"((c)[1]), "+f"((c)[2]), "+f"((c)[3])              \
        : "r"(a0), "r"(a1), "r"(a2), "r"(a3), "r"(b0), "r"(b1))

// ===========================================================================
// Prep kernels
// ===========================================================================
__global__ void __launch_bounds__(256) conv_x_k(const float* __restrict__ x)
{
    __shared__ float smT[128 * 66];
    int tile = blockIdx.x, tid = threadIdx.x;
    const float* xp = x + (size_t)tile * 8192;
    uint32_t* da = g_xA + (size_t)tile * 8192;
    for (int w = tid; w < 4096; w += 256) {
        int r = w >> 6, kp = w & 63;
        float2 v = *(const float2*)(xp + r * NN + 2 * kp);
        da[w]        = pack_h2(v.x, v.y);
        da[4096 + w] = pack_l2(v.x, v.y);
    }
    for (int i = tid; i < 8192; i += 256) {
        int r = i >> 7, n = i & 127;
        smT[n * 66 + r] = xp[i];
    }
    __syncthreads();
    uint32_t* db = g_xB + (size_t)tile * 4096;
    for (int w = tid; w < 4096; w += 256) {
        int n = w >> 5, kpf = w & 31;
        float2 v = *(const float2*)&smT[n * 66 + 2 * kpf];
        db[w] = pack_h2(v.x, v.y);
    }
}

__global__ void __launch_bounds__(256) conv_H_k(const float* __restrict__ H)
{
    int tid = threadIdx.x;
    for (int w = tid; w < 8 * 2048; w += 256) {
        int c = w >> 11, o = (w >> 5) & 63, kpf = w & 31;
        int e = c >> 2, k = c & 3;
        int off = e * 256 + k * 64;
        float a  = H[o * 512 + off + 2 * kpf];
        float b2 = H[o * 512 + off + 2 * kpf + 1];
        g_HA[c * 4096 + o * 32 + kpf]        = pack_h2(a, b2);
        g_HA[c * 4096 + 2048 + o * 32 + kpf] = pack_l2(a, b2);
    }
}

// ===========================================================================
// Diffusion: tap[pass][b,t,e] = in[b,t-1] @ S[b,t,e]
// pass 0: A = x (2-plane), converts S fp32->fp16, exports packed S to g_SB.
// passes 1,2: A = tap (1-plane), S by uint4 copy from g_SB (L2-resident).
// ===========================================================================
#define DA_H 0
#define DA_L 4352
#define DB   8704
#define D_WORDS 17408          // 69632 B -> 3 CTA/SM

__global__ void __launch_bounds__(256, 3) diffuse_k(
    const float* __restrict__ S, int pass)
{
    extern __shared__ __align__(16) uint32_t sm[];
    int idx = blockIdx.x;
    int e = idx & 1, t = (idx >> 1) & 63, b = idx >> 7;
    int tid = threadIdx.x;

    uint32_t* tb = g_tapB[pass] + (size_t)idx * 4096;
    uint32_t* ta = (pass < 2) ? g_tapA[pass] + (size_t)idx * 4096 : nullptr;

    if (t == 0) {
        uint4 z = make_uint4(0, 0, 0, 0);
        for (int w = tid; w < 1024; w += 256) ((uint4*)tb)[w] = z;
        if (pass < 2)
            for (int w = tid; w < 1024; w += 256) ((uint4*)ta)[w] = z;
        return;
    }

    // A fill
    if (pass == 0) {
        const uint4* asrc = (const uint4*)(g_xA + (size_t)(b * 64 + (t - 1)) * 8192);
        for (int w = tid; w < 1024; w += 256) {
            int r = w >> 4, q = w & 15;
            *(uint4*)&sm[DA_H + r * 68 + 4 * q] = asrc[w];
            *(uint4*)&sm[DA_L + r * 68 + 4 * q] = asrc[1024 + w];
        }
    } else {
        const uint4* asrc =
            (const uint4*)(g_tapA[pass - 1] + (size_t)((b * 64 + (t - 1)) * 2 + e) * 4096);
        for (int w = tid; w < 1024; w += 256) {
            int r = w >> 4, q = w & 15;
            *(uint4*)&sm[DA_H + r * 68 + 4 * q] = asrc[w];
        }
    }
    // B fill
    if (pass == 0) {
        const float* Sp = S + (size_t)((b * 64 + t) * 2 + e) * 16384;
        for (int i = tid; i < 8192; i += 256) {
            int n = i & 127, kp = i >> 7;
            sm[DB + n * 68 + kp] = pack_h2(Sp[(2 * kp) * NN + n], Sp[(2 * kp + 1) * NN + n]);
        }
    } else {
        const uint4* sbs = (const uint4*)(g_SB + (size_t)idx * 8192);
        for (int w = tid; w < 1024; w += 256) {
            int n = w >> 3, q = w & 7;
            *(uint4*)&sm[DB + n * 68 + 4 * q]      = sbs[w];
            *(uint4*)&sm[DB + n * 68 + 32 + 4 * q] = sbs[1024 + w];
        }
    }
    __syncthreads();

    // pass 0: export packed S (stores drain under the MMA phase)
    if (pass == 0) {
        uint32_t* sbo = g_SB + (size_t)idx * 8192;
        for (int w = tid; w < 1024; w += 256) {
            int n = w >> 3, q = w & 7;
            ((uint4*)sbo)[w]        = *(const uint4*)&sm[DB + n * 68 + 4 * q];
            ((uint4*)sbo)[1024 + w] = *(const uint4*)&sm[DB + n * 68 + 32 + 4 * q];
        }
    }

    int wid = tid >> 5, lane = tid & 31;
    int wm = wid & 3, wn = wid >> 2;
    int ra = lane >> 2, ca = lane & 3;
    int g = lane >> 3, lr = lane & 7;
    int arow = (g & 1) * 8 + lr, kcol = (g >> 1) * 4;
    uint32_t smb = smem_u32(sm);
    uint32_t aH = smb + (uint32_t)((DA_H + (16 * wm + arow) * 68 + kcol) * 4);
    uint32_t aL = smb + (uint32_t)((DA_L + (16 * wm + arow) * 68 + kcol) * 4);
    uint32_t bB = smb + (uint32_t)((DB + (64 * wn + arow) * 68 + kcol) * 4);

    float acc[8][4];
    #pragma unroll
    for (int nt = 0; nt < 8; nt++)
        acc[nt][0] = acc[nt][1] = acc[nt][2] = acc[nt][3] = 0.f;

    if (pass == 0) {
        #pragma unroll
        for (int k = 0; k < 8; k++) {
            uint32_t ah0, ah1, ah2, ah3, al0, al1, al2, al3;
            ldsm4(aH + k * 32, ah0, ah1, ah2, ah3);
            ldsm4(aL + k * 32, al0, al1, al2, al3);
            #pragma unroll
            for (int g2 = 0; g2 < 4; g2++) {
                uint32_t b0e, b0o, b1e, b1o;
                ldsm4(bB + g2 * (16 * 68 * 4) + k * 32, b0e, b0o, b1e, b1o);
                MMA_F16(acc[2 * g2],     ah0, ah1, ah2, ah3, b0e, b1e);
                MMA_F16(acc[2 * g2 + 1], ah0, ah1, ah2, ah3, b0o, b1o);
                MMA_F16(acc[2 * g2],     al0, al1, al2, al3, b0e, b1e);
                MMA_F16(acc[2 * g2 + 1], al0, al1, al2, al3, b0o, b1o);
            }
        }
    } else {
        #pragma unroll
        for (int k = 0; k < 8; k++) {
            uint32_t ah0, ah1, ah2, ah3;
            ldsm4(aH + k * 32, ah0, ah1, ah2, ah3);
            #pragma unroll
            for (int g2 = 0; g2 < 4; g2++) {
                uint32_t b0e, b0o, b1e, b1o;
                ldsm4(bB + g2 * (16 * 68 * 4) + k * 32, b0e, b0o, b1e, b1o);
                MMA_F16(acc[2 * g2],     ah0, ah1, ah2, ah3, b0e, b1e);
                MMA_F16(acc[2 * g2 + 1], ah0, ah1, ah2, ah3, b0o, b1o);
            }
        }
    }
    __syncthreads();   // all A/B smem reads done

    // stage tapA (A-format, single hi plane) into DA region
    if (pass < 2) {
        int r0 = 16 * wm + ra;
        #pragma unroll
        for (int nt = 0; nt < 8; nt++) {
            int kp = 32 * wn + 4 * nt + ca;
            sm[DA_H + r0 * 68 + kp]       = pack_h2(acc[nt][0], acc[nt][1]);
            sm[DA_H + (r0 + 8) * 68 + kp] = pack_h2(acc[nt][2], acc[nt][3]);
        }
    }
    // stage tapB (B64 single plane, stride 36) into DB region
    {
        #pragma unroll
        for (int nt = 0; nt < 8; nt++) {
            float o0 = __shfl_down_sync(0xffffffffu, acc[nt][0], 4);
            float o1 = __shfl_down_sync(0xffffffffu, acc[nt][1], 4);
            float o2 = __shfl_down_sync(0xffffffffu, acc[nt][2], 4);
            float o3 = __shfl_down_sync(0xffffffffu, acc[nt][3], 4);
            if (!(ra & 1)) {
                int c  = 64 * wn + nt * 8 + 2 * ca;
                int ka = 8 * wm + (ra >> 1);
                sm[DB + c * 36 + ka]           = pack_h2(acc[nt][0], o0);
                sm[DB + (c + 1) * 36 + ka]     = pack_h2(acc[nt][1], o1);
                sm[DB + c * 36 + ka + 4]       = pack_h2(acc[nt][2], o2);
                sm[DB + (c + 1) * 36 + ka + 4] = pack_h2(acc[nt][3], o3);
            }
        }
    }
    __syncthreads();

    if (pass < 2) {
        for (int w = tid; w < 1024; w += 256) {
            int r = w >> 4, q = w & 15;
            ((uint4*)ta)[w] = *(const uint4*)&sm[DA_H + r * 68 + 4 * q];
        }
    }
    for (int w = tid; w < 1024; w += 256) {
        int n = w >> 3, q = w & 7;
        ((uint4*)tb)[w] = *(const uint4*)&sm[DB + n * 36 + 4 * q];
    }
}

// ===========================================================================
// Projection: y[o][n] = bias[o] + sum_cc H_cc @ Z_cc  (unchanged from R14)
// ===========================================================================
#define P_BUF 9216
#define P_WORDS (2 * P_BUF)      // 73728 B -> 2 CTA/SM

__device__ __forceinline__ void proj_copy(uint32_t* sm, int cc, int bt, int tid)
{
    int e = cc >> 2, k = cc & 3;
    int buf = (cc & 1) * P_BUF;
    const uint4* hsrc = (const uint4*)(g_HA + (size_t)cc * 4096);
    for (int w = tid; w < 512; w += 256) {
        int o = w >> 3, q = w & 7;
        *(uint4*)&sm[buf + o * 36 + 4 * q]        = hsrc[w];
        *(uint4*)&sm[buf + 2304 + o * 36 + 4 * q] = hsrc[512 + w];
    }
    const uint4* zsrc = (k == 0)
        ? (const uint4*)(g_xB + (size_t)bt * 4096)
        : (const uint4*)(g_tapB[k - 1] + (size_t)(bt * 2 + e) * 4096);
    for (int w = tid; w < 1024; w += 256) {
        int n = w >> 3, q = w & 7;
        *(uint4*)&sm[buf + 4608 + n * 36 + 4 * q] = zsrc[w];
    }
}

__global__ void __launch_bounds__(256) proj_k(
    const float* __restrict__ bias, float* __restrict__ y)
{
    extern __shared__ __align__(16) uint32_t sm[];
    int t = blockIdx.x & 63, b = blockIdx.x >> 6;
    int bt = b * 64 + t;
    int tid = threadIdx.x;
    int wid = tid >> 5, lane = tid & 31;
    int wm = wid & 3, wn = wid >> 2;
    int ra = lane >> 2, ca = lane & 3;
    int g = lane >> 3, lr = lane & 7;
    int arow = (g & 1) * 8 + lr, kcol = (g >> 1) * 4;
    uint32_t smb = smem_u32(sm);

    float acc[8][4];
    #pragma unroll
    for (int nt = 0; nt < 8; nt++)
        acc[nt][0] = acc[nt][1] = acc[nt][2] = acc[nt][3] = 0.f;

    proj_copy(sm, 0, bt, tid);
    __syncthreads();

    for (int cc = 0; cc < 8; cc++) {
        if (cc < 7) proj_copy(sm, cc + 1, bt, tid);   // other buffer

        int buf = (cc & 1) * P_BUF;
        uint32_t aH = smb + (uint32_t)((buf + (16 * wm + arow) * 36 + kcol) * 4);
        uint32_t aL = smb + (uint32_t)((buf + 2304 + (16 * wm + arow) * 36 + kcol) * 4);
        uint32_t bB = smb + (uint32_t)((buf + 4608 + (64 * wn + arow) * 36 + kcol) * 4);
        #pragma unroll
        for (int kk = 0; kk < 4; kk++) {
            uint32_t ah0, ah1, ah2, ah3, al0, al1, al2, al3;
            ldsm4(aH + kk * 32, ah0, ah1, ah2, ah3);
            ldsm4(aL + kk * 32, al0, al1, al2, al3);
            #pragma unroll
            for (int g2 = 0; g2 < 4; g2++) {
                uint32_t b0e, b0o, b1e, b1o;
                ldsm4(bB + g2 * (16 * 36 * 4) + kk * 32, b0e, b0o, b1e, b1o);
                MMA_F16(acc[2 * g2],     ah0, ah1, ah2, ah3, b0e, b1e);
                MMA_F16(acc[2 * g2 + 1], ah0, ah1, ah2, ah3, b0o, b1o);
                MMA_F16(acc[2 * g2],     al0, al1, al2, al3, b0e, b1e);
                MMA_F16(acc[2 * g2 + 1], al0, al1, al2, al3, b0o, b1o);
            }
        }
        __syncthreads();
    }

    float* yp = y + (size_t)bt * 8192;
    int r0 = 16 * wm + ra;
    float bv0 = bias[r0], bv1 = bias[r0 + 8];
    #pragma unroll
    for (int nt = 0; nt < 8; nt++) {
        int c = 64 * wn + nt * 8 + 2 * ca;
        *(float2*)(yp + r0 * NN + c) =
            make_float2(acc[nt][0] + bv0, acc[nt][1] + bv0);
        *(float2*)(yp + (r0 + 8) * NN + c) =
            make_float2(acc[nt][2] + bv1, acc[nt][3] + bv1);
    }
}

// ---------------------------------------------------------------------------
extern "C" void kernel_launch(void* const* d_in, const int* in_sizes, int n_in,
                              void* d_out, int out_size)
{
    const float* x    = (const float*)d_in[0];
    const float* S    = (const float*)d_in[1];
    const float* H    = (const float*)d_in[2];
    const float* bias = (const float*)d_in[3];
    float* y = (float*)d_out;

    cudaFuncSetAttribute(diffuse_k, cudaFuncAttributeMaxDynamicSharedMemorySize,
                         D_WORDS * 4);
    cudaFuncSetAttribute(proj_k, cudaFuncAttributeMaxDynamicSharedMemorySize,
                         P_WORDS * 4);

    conv_x_k<<<1024, 256>>>(x);
    conv_H_k<<<1, 256>>>(H);

    for (int pass = 0; pass < 3; pass++)
        diffuse_k<<<16 * 64 * 2, 256, D_WORDS * 4>>>(S, pass);

    proj_k<<<16 * 64, 256, P_WORDS * 4>>>(bias, y);
}

// round 16
// speedup vs baseline: 1.3214x; 1.3214x over previous
#include <cuda_runtime.h>
#include <cuda_fp16.h>
#include <cstdint>

#define NN 128

// ---- packed global operands (fp16 planes, packed 2/word) -------------------
__device__ uint32_t g_xA[1024u * 8192u];      // x A-fmt [tile(b,t)]: hi r*64+kp (4096), lo +4096
__device__ uint32_t g_xB[1024u * 4096u];      // x B64 1-plane [tile(b,t)]: n*32+kpf
__device__ uint32_t g_SB[2048u * 8192u];      // S B-fmt 1-plane [tile(b,t,e)]: half0 | half1
__device__ uint32_t g_tapA[2][2048u * 8192u]; // taps 1,2 A-fmt 2-plane [tile(b,t,e)]
__device__ uint32_t g_tapB[3][2048u * 4096u]; // taps 1,2,3 B64 1-plane [tile(b,t,e)]
__device__ uint32_t g_HA[8u * 2048u];         // H chunks [e*4+k]: hi-only o*32+kpf

// ---------------------------------------------------------------------------
__device__ __forceinline__ uint32_t pack_h2(float a, float b) {
    uint32_t ua = (uint32_t)__half_as_ushort(__float2half_rn(a));
    uint32_t ub = (uint32_t)__half_as_ushort(__float2half_rn(b));
    return (ub << 16) | ua;
}
__device__ __forceinline__ uint32_t pack_l2(float a, float b) {
    __half ha = __float2half_rn(a), hb = __float2half_rn(b);
    float ra = a - __half2float(ha), rb = b - __half2float(hb);
    uint32_t ua = (uint32_t)__half_as_ushort(__float2half_rn(ra));
    uint32_t ub = (uint32_t)__half_as_ushort(__float2half_rn(rb));
    return (ub << 16) | ua;
}
__device__ __forceinline__ uint32_t smem_u32(const void* p) {
    uint32_t a;
    asm("{ .reg .u64 t; cvta.to.shared.u64 t, %1; cvt.u32.u64 %0, t; }" : "=r"(a) : "l"(p));
    return a;
}
__device__ __forceinline__ void ldsm4(uint32_t a, uint32_t& r0, uint32_t& r1,
                                      uint32_t& r2, uint32_t& r3) {
    asm volatile("ldmatrix.sync.aligned.m8n8.x4.shared.b16 {%0,%1,%2,%3}, [%4];"
                 : "=r"(r0), "=r"(r1), "=r"(r2), "=r"(r3) : "r"(a));
}

#define MMA_F16(c, a0, a1, a2, a3, b0, b1)                                    \
    asm volatile(                                                             \
        "mma.sync.aligned.m16n8k16.row.col.f32.f16.f16.f32 "                  \
        "{%0,%1,%2,%3}, {%4,%5,%6,%7}, {%8,%9}, {%0,%1,%2,%3};"               \
        : "+f"((c)[0]), "+f"((c)[1]), "+f"((c)[2]), "+f"((c)[3])              \
        : "r"(a0), "r"(a1), "r"(a2), "r"(a3), "r"(b0), "r"(b1))

// ===========================================================================
// Prep kernels
// ===========================================================================
__global__ void __launch_bounds__(256) conv_x_k(const float* __restrict__ x)
{
    __shared__ float smT[128 * 66];
    int tile = blockIdx.x, tid = threadIdx.x;
    const float* xp = x + (size_t)tile * 8192;
    uint32_t* da = g_xA + (size_t)tile * 8192;
    for (int w = tid; w < 4096; w += 256) {
        int r = w >> 6, kp = w & 63;
        float2 v = *(const float2*)(xp + r * NN + 2 * kp);
        da[w]        = pack_h2(v.x, v.y);
        da[4096 + w] = pack_l2(v.x, v.y);
    }
    for (int i = tid; i < 8192; i += 256) {
        int r = i >> 7, n = i & 127;
        smT[n * 66 + r] = xp[i];
    }
    __syncthreads();
    uint32_t* db = g_xB + (size_t)tile * 4096;
    for (int w = tid; w < 4096; w += 256) {
        int n = w >> 5, kpf = w & 31;
        float2 v = *(const float2*)&smT[n * 66 + 2 * kpf];
        db[w] = pack_h2(v.x, v.y);
    }
}

__global__ void __launch_bounds__(256) conv_H_k(const float* __restrict__ H)
{
    int tid = threadIdx.x;
    for (int w = tid; w < 8 * 2048; w += 256) {
        int c = w >> 11, o = (w >> 5) & 63, kpf = w & 31;
        int e = c >> 2, k = c & 3;
        int off = e * 256 + k * 64;
        float a  = H[o * 512 + off + 2 * kpf];
        float b2 = H[o * 512 + off + 2 * kpf + 1];
        g_HA[c * 2048 + o * 32 + kpf] = pack_h2(a, b2);
    }
}

// ===========================================================================
// Diffusion (identical to R14): tap[pass][b,t,e] = in[b,t-1] @ S[b,t,e]
// pass 0: converts S fp32 -> fp16 in smem, exports packed S to g_SB.
// passes 1,2: fill S by pure uint4 copies from g_SB.
// ===========================================================================
#define DA_H 0
#define DA_L 4352
#define DB   8704
#define D_WORDS 17408          // 69632 B -> 3 CTA/SM

__global__ void __launch_bounds__(256, 3) diffuse_k(
    const float* __restrict__ S, int pass)
{
    extern __shared__ __align__(16) uint32_t sm[];
    int idx = blockIdx.x;
    int e = idx & 1, t = (idx >> 1) & 63, b = idx >> 7;
    int tid = threadIdx.x;

    uint32_t* tb = g_tapB[pass] + (size_t)idx * 4096;
    uint32_t* ta = (pass < 2) ? g_tapA[pass] + (size_t)idx * 8192 : nullptr;

    if (t == 0) {
        uint4 z = make_uint4(0, 0, 0, 0);
        for (int w = tid; w < 1024; w += 256) ((uint4*)tb)[w] = z;
        if (pass < 2)
            for (int w = tid; w < 2048; w += 256) ((uint4*)ta)[w] = z;
        return;
    }

    {
        const uint4* asrc = (pass == 0)
            ? (const uint4*)(g_xA + (size_t)(b * 64 + (t - 1)) * 8192)
            : (const uint4*)(g_tapA[pass - 1] + (size_t)((b * 64 + (t - 1)) * 2 + e) * 8192);
        for (int w = tid; w < 1024; w += 256) {
            int r = w >> 4, q = w & 15;
            *(uint4*)&sm[DA_H + r * 68 + 4 * q] = asrc[w];
            *(uint4*)&sm[DA_L + r * 68 + 4 * q] = asrc[1024 + w];
        }
    }
    if (pass == 0) {
        const float* Sp = S + (size_t)((b * 64 + t) * 2 + e) * 16384;
        for (int i = tid; i < 8192; i += 256) {
            int n = i & 127, kp = i >> 7;
            sm[DB + n * 68 + kp] = pack_h2(Sp[(2 * kp) * NN + n], Sp[(2 * kp + 1) * NN + n]);
        }
    } else {
        const uint4* sbs = (const uint4*)(g_SB + (size_t)idx * 8192);
        for (int w = tid; w < 1024; w += 256) {
            int n = w >> 3, q = w & 7;
            *(uint4*)&sm[DB + n * 68 + 4 * q]      = sbs[w];
            *(uint4*)&sm[DB + n * 68 + 32 + 4 * q] = sbs[1024 + w];
        }
    }
    __syncthreads();

    if (pass == 0) {
        uint32_t* sbo = g_SB + (size_t)idx * 8192;
        for (int w = tid; w < 1024; w += 256) {
            int n = w >> 3, q = w & 7;
            ((uint4*)sbo)[w]        = *(const uint4*)&sm[DB + n * 68 + 4 * q];
            ((uint4*)sbo)[1024 + w] = *(const uint4*)&sm[DB + n * 68 + 32 + 4 * q];
        }
    }

    int wid = tid >> 5, lane = tid & 31;
    int wm = wid & 3, wn = wid >> 2;
    int ra = lane >> 2, ca = lane & 3;
    int g = lane >> 3, lr = lane & 7;
    int arow = (g & 1) * 8 + lr, kcol = (g >> 1) * 4;
    uint32_t smb = smem_u32(sm);
    uint32_t aH = smb + (uint32_t)((DA_H + (16 * wm + arow) * 68 + kcol) * 4);
    uint32_t aL = smb + (uint32_t)((DA_L + (16 * wm + arow) * 68 + kcol) * 4);
    uint32_t bB = smb + (uint32_t)((DB + (64 * wn + arow) * 68 + kcol) * 4);

    float acc[8][4];
    #pragma unroll
    for (int nt = 0; nt < 8; nt++)
        acc[nt][0] = acc[nt][1] = acc[nt][2] = acc[nt][3] = 0.f;

    #pragma unroll
    for (int k = 0; k < 8; k++) {
        uint32_t ah0, ah1, ah2, ah3, al0, al1, al2, al3;
        ldsm4(aH + k * 32, ah0, ah1, ah2, ah3);
        ldsm4(aL + k * 32, al0, al1, al2, al3);
        #pragma unroll
        for (int g2 = 0; g2 < 4; g2++) {
            uint32_t b0e, b0o, b1e, b1o;
            ldsm4(bB + g2 * (16 * 68 * 4) + k * 32, b0e, b0o, b1e, b1o);
            MMA_F16(acc[2 * g2],     ah0, ah1, ah2, ah3, b0e, b1e);
            MMA_F16(acc[2 * g2 + 1], ah0, ah1, ah2, ah3, b0o, b1o);
            MMA_F16(acc[2 * g2],     al0, al1, al2, al3, b0e, b1e);
            MMA_F16(acc[2 * g2 + 1], al0, al1, al2, al3, b0o, b1o);
        }
    }
    __syncthreads();

    if (pass < 2) {
        int r0 = 16 * wm + ra;
        #pragma unroll
        for (int nt = 0; nt < 8; nt++) {
            int kp = 32 * wn + 4 * nt + ca;
            sm[DA_H + r0 * 68 + kp]       = pack_h2(acc[nt][0], acc[nt][1]);
            sm[DA_L + r0 * 68 + kp]       = pack_l2(acc[nt][0], acc[nt][1]);
            sm[DA_H + (r0 + 8) * 68 + kp] = pack_h2(acc[nt][2], acc[nt][3]);
            sm[DA_L + (r0 + 8) * 68 + kp] = pack_l2(acc[nt][2], acc[nt][3]);
        }
    }
    {
        #pragma unroll
        for (int nt = 0; nt < 8; nt++) {
            float o0 = __shfl_down_sync(0xffffffffu, acc[nt][0], 4);
            float o1 = __shfl_down_sync(0xffffffffu, acc[nt][1], 4);
            float o2 = __shfl_down_sync(0xffffffffu, acc[nt][2], 4);
            float o3 = __shfl_down_sync(0xffffffffu, acc[nt][3], 4);
            if (!(ra & 1)) {
                int c  = 64 * wn + nt * 8 + 2 * ca;
                int ka = 8 * wm + (ra >> 1);
                sm[DB + c * 36 + ka]           = pack_h2(acc[nt][0], o0);
                sm[DB + (c + 1) * 36 + ka]     = pack_h2(acc[nt][1], o1);
                sm[DB + c * 36 + ka + 4]       = pack_h2(acc[nt][2], o2);
                sm[DB + (c + 1) * 36 + ka + 4] = pack_h2(acc[nt][3], o3);
            }
        }
    }
    __syncthreads();

    if (pass < 2) {
        for (int w = tid; w < 1024; w += 256) {
            int r = w >> 4, q = w & 15;
            ((uint4*)ta)[w]        = *(const uint4*)&sm[DA_H + r * 68 + 4 * q];
            ((uint4*)ta)[1024 + w] = *(const uint4*)&sm[DA_L + r * 68 + 4 * q];
        }
    }
    for (int w = tid; w < 1024; w += 256) {
        int n = w >> 3, q = w & 7;
        ((uint4*)tb)[w] = *(const uint4*)&sm[DB + n * 36 + 4 * q];
    }
}

// ===========================================================================
// Projection (R13 structure, single-plane H): y = bias + sum_cc H_cc @ Z_cc
// smem per buf @ buf*6912: PH 0 (2304 words) | PZ 2304 (4608 words)
// ===========================================================================
#define P_BUF 6912
#define P_WORDS (2 * P_BUF)      // 55296 B -> 3 CTA/SM

__device__ __forceinline__ void proj_copy(uint32_t* sm, int cc, int bt, int tid)
{
    int e = cc >> 2, k = cc & 3;
    int buf = (cc & 1) * P_BUF;
    const uint4* hsrc = (const uint4*)(g_HA + (size_t)cc * 2048);
    for (int w = tid; w < 512; w += 256) {
        int o = w >> 3, q = w & 7;
        *(uint4*)&sm[buf + o * 36 + 4 * q] = hsrc[w];
    }
    const uint4* zsrc = (k == 0)
        ? (const uint4*)(g_xB + (size_t)bt * 4096)
        : (const uint4*)(g_tapB[k - 1] + (size_t)(bt * 2 + e) * 4096);
    for (int w = tid; w < 1024; w += 256) {
        int n = w >> 3, q = w & 7;
        *(uint4*)&sm[buf + 2304 + n * 36 + 4 * q] = zsrc[w];
    }
}

__global__ void __launch_bounds__(256) proj_k(
    const float* __restrict__ bias, float* __restrict__ y)
{
    extern __shared__ __align__(16) uint32_t sm[];
    int t = blockIdx.x & 63, b = blockIdx.x >> 6;
    int bt = b * 64 + t;
    int tid = threadIdx.x;
    int wid = tid >> 5, lane = tid & 31;
    int wm = wid & 3, wn = wid >> 2;
    int ra = lane >> 2, ca = lane & 3;
    int g = lane >> 3, lr = lane & 7;
    int arow = (g & 1) * 8 + lr, kcol = (g >> 1) * 4;
    uint32_t smb = smem_u32(sm);

    float acc[8][4];
    #pragma unroll
    for (int nt = 0; nt < 8; nt++)
        acc[nt][0] = acc[nt][1] = acc[nt][2] = acc[nt][3] = 0.f;

    for (int cc = 0; cc < 8; cc++) {
        proj_copy(sm, cc, bt, tid);
        __syncthreads();

        int buf = (cc & 1) * P_BUF;
        uint32_t aH = smb + (uint32_t)((buf + (16 * wm + arow) * 36 + kcol) * 4);
        uint32_t bB = smb + (uint32_t)((buf + 2304 + (64 * wn + arow) * 36 + kcol) * 4);
        #pragma unroll
        for (int kk = 0; kk < 4; kk++) {
            uint32_t ah0, ah1, ah2, ah3;
            ldsm4(aH + kk * 32, ah0, ah1, ah2, ah3);
            #pragma unroll
            for (int g2 = 0; g2 < 4; g2++) {
                uint32_t b0e, b0o, b1e, b1o;
                ldsm4(bB + g2 * (16 * 36 * 4) + kk * 32, b0e, b0o, b1e, b1o);
                MMA_F16(acc[2 * g2],     ah0, ah1, ah2, ah3, b0e, b1e);
                MMA_F16(acc[2 * g2 + 1], ah0, ah1, ah2, ah3, b0o, b1o);
            }
        }
    }

    float* yp = y + (size_t)bt * 8192;
    int r0 = 16 * wm + ra;
    float bv0 = bias[r0], bv1 = bias[r0 + 8];
    #pragma unroll
    for (int nt = 0; nt < 8; nt++) {
        int c = 64 * wn + nt * 8 + 2 * ca;
        *(float2*)(yp + r0 * NN + c) =
            make_float2(acc[nt][0] + bv0, acc[nt][1] + bv0);
        *(float2*)(yp + (r0 + 8) * NN + c) =
            make_float2(acc[nt][2] + bv1, acc[nt][3] + bv1);
    }
}

// ---------------------------------------------------------------------------
extern "C" void kernel_launch(void* const* d_in, const int* in_sizes, int n_in,
                              void* d_out, int out_size)
{
    const float* x    = (const float*)d_in[0];
    const float* S    = (const float*)d_in[1];
    const float* H    = (const float*)d_in[2];
    const float* bias = (const float*)d_in[3];
    float* y = (float*)d_out;

    cudaFuncSetAttribute(diffuse_k, cudaFuncAttributeMaxDynamicSharedMemorySize,
                         D_WORDS * 4);
    cudaFuncSetAttribute(proj_k, cudaFuncAttributeMaxDynamicSharedMemorySize,
                         P_WORDS * 4);

    conv_x_k<<<1024, 256>>>(x);
    conv_H_k<<<1, 256>>>(H);

    for (int pass = 0; pass < 3; pass++)
        diffuse_k<<<16 * 64 * 2, 256, D_WORDS * 4>>>(S, pass);

    proj_k<<<16 * 64, 256, P_WORDS * 4>>>(bias, y);
}

// round 17
// speedup vs baseline: 1.5301x; 1.1579x over previous
#include <cuda_runtime.h>
#include <cuda_fp16.h>
#include <cstdint>

#define NN 128

// ---- packed global operands (fp16, packed 2/word, single plane) ------------
__device__ uint32_t g_xA[1024u * 4096u];      // x A-fmt hi [tile(b,t)]: r*64+kp
__device__ uint32_t g_xB[1024u * 4096u];      // x B64 [tile(b,t)]: n*32+kpf
__device__ uint32_t g_SB[2048u * 8192u];      // S B-fmt [tile(b,t,e)]: half0 | half1
__device__ uint32_t g_tapA[2][2048u * 4096u]; // taps 1,2 A-fmt hi [tile(b,t,e)]
__device__ uint32_t g_tapB[3][2048u * 4096u]; // taps 1,2,3 B64 [tile(b,t,e)]
__device__ uint32_t g_HA[8u * 2048u];         // H chunks [e*4+k]: hi o*32+kpf

// ---------------------------------------------------------------------------
__device__ __forceinline__ uint32_t pack_h2(float a, float b) {
    uint32_t ua = (uint32_t)__half_as_ushort(__float2half_rn(a));
    uint32_t ub = (uint32_t)__half_as_ushort(__float2half_rn(b));
    return (ub << 16) | ua;
}
__device__ __forceinline__ uint32_t smem_u32(const void* p) {
    uint32_t a;
    asm("{ .reg .u64 t; cvta.to.shared.u64 t, %1; cvt.u32.u64 %0, t; }" : "=r"(a) : "l"(p));
    return a;
}
__device__ __forceinline__ void ldsm4(uint32_t a, uint32_t& r0, uint32_t& r1,
                                      uint32_t& r2, uint32_t& r3) {
    asm volatile("ldmatrix.sync.aligned.m8n8.x4.shared.b16 {%0,%1,%2,%3}, [%4];"
                 : "=r"(r0), "=r"(r1), "=r"(r2), "=r"(r3) : "r"(a));
}

#define MMA_F16(c, a0, a1, a2, a3, b0, b1)                                    \
    asm volatile(                                                             \
        "mma.sync.aligned.m16n8k16.row.col.f32.f16.f16.f32 "                  \
        "{%0,%1,%2,%3}, {%4,%5,%6,%7}, {%8,%9}, {%0,%1,%2,%3};"               \
        : "+f"((c)[0]), "+f"((c)[1]), "+f"((c)[2]), "+f"((c)[3])              \
        : "r"(a0), "r"(a1), "r"(a2), "r"(a3), "r"(b0), "r"(b1))

// ===========================================================================
// Prep kernels
// ===========================================================================
__global__ void __launch_bounds__(256) conv_x_k(const float* __restrict__ x)
{
    __shared__ float smT[128 * 66];
    int tile = blockIdx.x, tid = threadIdx.x;
    const float* xp = x + (size_t)tile * 8192;
    uint32_t* da = g_xA + (size_t)tile * 4096;
    for (int w = tid; w < 4096; w += 256) {
        int r = w >> 6, kp = w & 63;
        float2 v = *(const float2*)(xp + r * NN + 2 * kp);
        da[w] = pack_h2(v.x, v.y);
    }
    for (int i = tid; i < 8192; i += 256) {
        int r = i >> 7, n = i & 127;
        smT[n * 66 + r] = xp[i];
    }
    __syncthreads();
    uint32_t* db = g_xB + (size_t)tile * 4096;
    for (int w = tid; w < 4096; w += 256) {
        int n = w >> 5, kpf = w & 31;
        float2 v = *(const float2*)&smT[n * 66 + 2 * kpf];
        db[w] = pack_h2(v.x, v.y);
    }
}

__global__ void __launch_bounds__(256) conv_H_k(const float* __restrict__ H)
{
    int tid = threadIdx.x;
    for (int w = tid; w < 8 * 2048; w += 256) {
        int c = w >> 11, o = (w >> 5) & 63, kpf = w & 31;
        int e = c >> 2, k = c & 3;
        int off = e * 256 + k * 64;
        float a  = H[o * 512 + off + 2 * kpf];
        float b2 = H[o * 512 + off + 2 * kpf + 1];
        g_HA[c * 2048 + o * 32 + kpf] = pack_h2(a, b2);
    }
}

// ===========================================================================
// Diffusion: tap[pass][b,t,e] = in[b,t-1] @ S[b,t,e]
// A = single hi-plane fp16 (x for pass 0, tapA otherwise), 64 MMAs/warp.
// pass 0 converts S fp32->fp16 and exports packed S to g_SB; passes 1,2 copy.
// smem: DA 0 (4352 words) | DB 4352 (8704 words) = 52224 B -> 4 CTA/SM
// ===========================================================================
#define DA   0
#define DB   4352
#define D_WORDS 13056

__global__ void __launch_bounds__(256, 4) diffuse_k(
    const float* __restrict__ S, int pass)
{
    extern __shared__ __align__(16) uint32_t sm[];
    int idx = blockIdx.x;
    int e = idx & 1, t = (idx >> 1) & 63, b = idx >> 7;
    int tid = threadIdx.x;

    uint32_t* tb = g_tapB[pass] + (size_t)idx * 4096;
    uint32_t* ta = (pass < 2) ? g_tapA[pass] + (size_t)idx * 4096 : nullptr;

    if (t == 0) {
        uint4 z = make_uint4(0, 0, 0, 0);
        for (int w = tid; w < 1024; w += 256) ((uint4*)tb)[w] = z;
        if (pass < 2)
            for (int w = tid; w < 1024; w += 256) ((uint4*)ta)[w] = z;
        return;
    }

    // A fill: single plane, uint4 copy
    {
        const uint4* asrc = (pass == 0)
            ? (const uint4*)(g_xA + (size_t)(b * 64 + (t - 1)) * 4096)
            : (const uint4*)(g_tapA[pass - 1] + (size_t)((b * 64 + (t - 1)) * 2 + e) * 4096);
        for (int w = tid; w < 1024; w += 256) {
            int r = w >> 4, q = w & 15;
            *(uint4*)&sm[DA + r * 68 + 4 * q] = asrc[w];
        }
    }
    // B fill
    if (pass == 0) {
        const float* Sp = S + (size_t)((b * 64 + t) * 2 + e) * 16384;
        for (int i = tid; i < 8192; i += 256) {
            int n = i & 127, kp = i >> 7;
            sm[DB + n * 68 + kp] = pack_h2(Sp[(2 * kp) * NN + n], Sp[(2 * kp + 1) * NN + n]);
        }
    } else {
        const uint4* sbs = (const uint4*)(g_SB + (size_t)idx * 8192);
        for (int w = tid; w < 1024; w += 256) {
            int n = w >> 3, q = w & 7;
            *(uint4*)&sm[DB + n * 68 + 4 * q]      = sbs[w];
            *(uint4*)&sm[DB + n * 68 + 32 + 4 * q] = sbs[1024 + w];
        }
    }
    __syncthreads();

    // pass 0: export packed S (stores drain under the MMA phase)
    if (pass == 0) {
        uint32_t* sbo = g_SB + (size_t)idx * 8192;
        for (int w = tid; w < 1024; w += 256) {
            int n = w >> 3, q = w & 7;
            ((uint4*)sbo)[w]        = *(const uint4*)&sm[DB + n * 68 + 4 * q];
            ((uint4*)sbo)[1024 + w] = *(const uint4*)&sm[DB + n * 68 + 32 + 4 * q];
        }
    }

    int wid = tid >> 5, lane = tid & 31;
    int wm = wid & 3, wn = wid >> 2;
    int ra = lane >> 2, ca = lane & 3;
    int g = lane >> 3, lr = lane & 7;
    int arow = (g & 1) * 8 + lr, kcol = (g >> 1) * 4;
    uint32_t smb = smem_u32(sm);
    uint32_t aA = smb + (uint32_t)((DA + (16 * wm + arow) * 68 + kcol) * 4);
    uint32_t bB = smb + (uint32_t)((DB + (64 * wn + arow) * 68 + kcol) * 4);

    float acc[8][4];
    #pragma unroll
    for (int nt = 0; nt < 8; nt++)
        acc[nt][0] = acc[nt][1] = acc[nt][2] = acc[nt][3] = 0.f;

    #pragma unroll
    for (int k = 0; k < 8; k++) {
        uint32_t a0, a1, a2, a3;
        ldsm4(aA + k * 32, a0, a1, a2, a3);
        #pragma unroll
        for (int g2 = 0; g2 < 4; g2++) {
            uint32_t b0e, b0o, b1e, b1o;
            ldsm4(bB + g2 * (16 * 68 * 4) + k * 32, b0e, b0o, b1e, b1o);
            MMA_F16(acc[2 * g2],     a0, a1, a2, a3, b0e, b1e);
            MMA_F16(acc[2 * g2 + 1], a0, a1, a2, a3, b0o, b1o);
        }
    }
    __syncthreads();   // all A/B smem reads done

    // stage tapA (A-format hi plane) into DA region
    if (pass < 2) {
        int r0 = 16 * wm + ra;
        #pragma unroll
        for (int nt = 0; nt < 8; nt++) {
            int kp = 32 * wn + 4 * nt + ca;
            sm[DA + r0 * 68 + kp]       = pack_h2(acc[nt][0], acc[nt][1]);
            sm[DA + (r0 + 8) * 68 + kp] = pack_h2(acc[nt][2], acc[nt][3]);
        }
    }
    // stage tapB (B64, stride 36) into DB region
    {
        #pragma unroll
        for (int nt = 0; nt < 8; nt++) {
            float o0 = __shfl_down_sync(0xffffffffu, acc[nt][0], 4);
            float o1 = __shfl_down_sync(0xffffffffu, acc[nt][1], 4);
            float o2 = __shfl_down_sync(0xffffffffu, acc[nt][2], 4);
            float o3 = __shfl_down_sync(0xffffffffu, acc[nt][3], 4);
            if (!(ra & 1)) {
                int c  = 64 * wn + nt * 8 + 2 * ca;
                int ka = 8 * wm + (ra >> 1);
                sm[DB + c * 36 + ka]           = pack_h2(acc[nt][0], o0);
                sm[DB + (c + 1) * 36 + ka]     = pack_h2(acc[nt][1], o1);
                sm[DB + c * 36 + ka + 4]       = pack_h2(acc[nt][2], o2);
                sm[DB + (c + 1) * 36 + ka + 4] = pack_h2(acc[nt][3], o3);
            }
        }
    }
    __syncthreads();

    if (pass < 2) {
        for (int w = tid; w < 1024; w += 256) {
            int r = w >> 4, q = w & 15;
            ((uint4*)ta)[w] = *(const uint4*)&sm[DA + r * 68 + 4 * q];
        }
    }
    for (int w = tid; w < 1024; w += 256) {
        int n = w >> 3, q = w & 7;
        ((uint4*)tb)[w] = *(const uint4*)&sm[DB + n * 36 + 4 * q];
    }
}

// ===========================================================================
// Projection (unchanged from R16): y = bias + sum_cc H_cc @ Z_cc
// smem per buf @ buf*6912: PH 0 (2304 words) | PZ 2304 (4608 words)
// ===========================================================================
#define P_BUF 6912
#define P_WORDS (2 * P_BUF)      // 55296 B -> 3 CTA/SM

__device__ __forceinline__ void proj_copy(uint32_t* sm, int cc, int bt, int tid)
{
    int e = cc >> 2, k = cc & 3;
    int buf = (cc & 1) * P_BUF;
    const uint4* hsrc = (const uint4*)(g_HA + (size_t)cc * 2048);
    for (int w = tid; w < 512; w += 256) {
        int o = w >> 3, q = w & 7;
        *(uint4*)&sm[buf + o * 36 + 4 * q] = hsrc[w];
    }
    const uint4* zsrc = (k == 0)
        ? (const uint4*)(g_xB + (size_t)bt * 4096)
        : (const uint4*)(g_tapB[k - 1] + (size_t)(bt * 2 + e) * 4096);
    for (int w = tid; w < 1024; w += 256) {
        int n = w >> 3, q = w & 7;
        *(uint4*)&sm[buf + 2304 + n * 36 + 4 * q] = zsrc[w];
    }
}

__global__ void __launch_bounds__(256) proj_k(
    const float* __restrict__ bias, float* __restrict__ y)
{
    extern __shared__ __align__(16) uint32_t sm[];
    int t = blockIdx.x & 63, b = blockIdx.x >> 6;
    int bt = b * 64 + t;
    int tid = threadIdx.x;
    int wid = tid >> 5, lane = tid & 31;
    int wm = wid & 3, wn = wid >> 2;
    int ra = lane >> 2, ca = lane & 3;
    int g = lane >> 3, lr = lane & 7;
    int arow = (g & 1) * 8 + lr, kcol = (g >> 1) * 4;
    uint32_t smb = smem_u32(sm);

    float acc[8][4];
    #pragma unroll
    for (int nt = 0; nt < 8; nt++)
        acc[nt][0] = acc[nt][1] = acc[nt][2] = acc[nt][3] = 0.f;

    for (int cc = 0; cc < 8; cc++) {
        proj_copy(sm, cc, bt, tid);
        __syncthreads();

        int buf = (cc & 1) * P_BUF;
        uint32_t aH = smb + (uint32_t)((buf + (16 * wm + arow) * 36 + kcol) * 4);
        uint32_t bB = smb + (uint32_t)((buf + 2304 + (64 * wn + arow) * 36 + kcol) * 4);
        #pragma unroll
        for (int kk = 0; kk < 4; kk++) {
            uint32_t ah0, ah1, ah2, ah3;
            ldsm4(aH + kk * 32, ah0, ah1, ah2, ah3);
            #pragma unroll
            for (int g2 = 0; g2 < 4; g2++) {
                uint32_t b0e, b0o, b1e, b1o;
                ldsm4(bB + g2 * (16 * 36 * 4) + kk * 32, b0e, b0o, b1e, b1o);
                MMA_F16(acc[2 * g2],     ah0, ah1, ah2, ah3, b0e, b1e);
                MMA_F16(acc[2 * g2 + 1], ah0, ah1, ah2, ah3, b0o, b1o);
            }
        }
    }

    float* yp = y + (size_t)bt * 8192;
    int r0 = 16 * wm + ra;
    float bv0 = bias[r0], bv1 = bias[r0 + 8];
    #pragma unroll
    for (int nt = 0; nt < 8; nt++) {
        int c = 64 * wn + nt * 8 + 2 * ca;
        *(float2*)(yp + r0 * NN + c) =
            make_float2(acc[nt][0] + bv0, acc[nt][1] + bv0);
        *(float2*)(yp + (r0 + 8) * NN + c) =
            make_float2(acc[nt][2] + bv1, acc[nt][3] + bv1);
    }
}

// ---------------------------------------------------------------------------
extern "C" void kernel_launch(void* const* d_in, const int* in_sizes, int n_in,
                              void* d_out, int out_size)
{
    const float* x    = (const float*)d_in[0];
    const float* S    = (const float*)d_in[1];
    const float* H    = (const float*)d_in[2];
    const float* bias = (const float*)d_in[3];
    float* y = (float*)d_out;

    cudaFuncSetAttribute(diffuse_k, cudaFuncAttributeMaxDynamicSharedMemorySize,
                         D_WORDS * 4);
    cudaFuncSetAttribute(proj_k, cudaFuncAttributeMaxDynamicSharedMemorySize,
                         P_WORDS * 4);

    conv_x_k<<<1024, 256>>>(x);
    conv_H_k<<<1, 256>>>(H);

    for (int pass = 0; pass < 3; pass++)
        diffuse_k<<<16 * 64 * 2, 256, D_WORDS * 4>>>(S, pass);

    proj_k<<<16 * 64, 256, P_WORDS * 4>>>(bias, y);
}